// round 3
// baseline (speedup 1.0000x reference)
#include <cuda_runtime.h>

// ---------------------------------------------------------------------------
// GCNEncoder: 2-layer GCN with self-loops + symmetric degree normalization.
//   deg[i]  = indeg(i) + 1
//   dinv[i] = rsqrt(deg[i])
//   layer(X,W,b): H = X@W
//                 A[i] = dinv[i]^2*H[i] + sum_{e: dst[e]=i} dinv[src]*dinv[i]*H[src]
//                 out  = A + b
//   out = layer2( relu(layer1(x)) )
//
// edge_index is int32 (JAX default config demotes int64 -> int32).
// No host-side CUDA API other than kernel launches (graph-capture safe).
// Scratch buffers are __device__ globals resolved inside device code.
// ---------------------------------------------------------------------------

#define MAXN 50000
#define FIN  128
#define HID  128
#define FOUT 64

__device__ float g_h1 [MAXN * HID];   // GEMM1 output / relu output
__device__ float g_agg[MAXN * HID];   // layer1 aggregation
__device__ float g_h2 [MAXN * FOUT];  // GEMM2 output
__device__ float g_dinv[MAXN];
__device__ int   g_deg [MAXN];

// Buffer selector: IDs 0..2 are device globals, 3 = external pointer argument.
template <int ID>
__device__ __forceinline__ float* gbuf(float* ext) {
    if constexpr (ID == 0) return g_h1;
    else if constexpr (ID == 1) return g_agg;
    else if constexpr (ID == 2) return g_h2;
    else return ext;
}

// ---------------------------------------------------------------------------
__global__ void deg_init_k(int n) {
    int i = blockIdx.x * blockDim.x + threadIdx.x;
    if (i < n) g_deg[i] = 1;   // self-loop
}

__global__ void deg_count_k(const int* __restrict__ dst, int E) {
    int i = blockIdx.x * blockDim.x + threadIdx.x;
    if (i < E) atomicAdd(&g_deg[dst[i]], 1);
}

__global__ void dinv_k(int n) {
    int i = blockIdx.x * blockDim.x + threadIdx.x;
    if (i < n) g_dinv[i] = rsqrtf((float)g_deg[i]);
}

// ---------------------------------------------------------------------------
// GEMM: O[n, NC] = X[n, K] @ W[K, NC].  256 threads/block.
// Each thread owns 4 output columns of one row (float4 on W, L1-resident).
// X rows staged in smem and broadcast over the k loop.
template <int K, int NC, int XID, int OID>
__global__ void __launch_bounds__(256)
gemm_k(const float* __restrict__ Xext, float* __restrict__ Oext,
       const float* __restrict__ W, int n) {
    const float* X = gbuf<XID>(const_cast<float*>(Xext));
    float*       O = gbuf<OID>(Oext);

    constexpr int CG  = NC / 4;     // float4 column-groups per row
    constexpr int RPB = 256 / CG;   // rows per block
    __shared__ float xs[RPB][K];

    const int row0 = blockIdx.x * RPB;
    for (int idx = threadIdx.x; idx < RPB * K; idx += 256) {
        int rr = idx / K, kk = idx % K;
        int grow = row0 + rr;
        xs[rr][kk] = (grow < n) ? X[(long long)grow * K + kk] : 0.f;
    }
    __syncthreads();

    const int r  = threadIdx.x / CG;
    const int cg = threadIdx.x % CG;
    const int grow = row0 + r;
    if (grow >= n) return;

    const float4* __restrict__ W4 = reinterpret_cast<const float4*>(W);
    float4 acc = make_float4(0.f, 0.f, 0.f, 0.f);
#pragma unroll
    for (int k = 0; k < K; k++) {
        float  xv = xs[r][k];
        float4 w  = W4[k * CG + cg];
        acc.x += xv * w.x; acc.y += xv * w.y;
        acc.z += xv * w.z; acc.w += xv * w.w;
    }
    reinterpret_cast<float4*>(O)[(long long)grow * CG + cg] = acc;
}

// ---------------------------------------------------------------------------
// Self-loop init: O[i,:] = dinv[i]^2 * H[i,:]
template <int F, int HID_, int OID>
__global__ void selfinit_k(float* __restrict__ Hext, float* __restrict__ Oext, int n) {
    const float* H = gbuf<HID_>(Hext);
    float*       O = gbuf<OID>(Oext);
    constexpr int F4 = F / 4;
    int gid = blockIdx.x * blockDim.x + threadIdx.x;
    if (gid >= n * F4) return;
    int i = gid / F4;
    float d = g_dinv[i];
    float s = d * d;
    float4 h = reinterpret_cast<const float4*>(H)[gid];
    reinterpret_cast<float4*>(O)[gid] = make_float4(h.x*s, h.y*s, h.z*s, h.w*s);
}

// ---------------------------------------------------------------------------
// Edge scatter: O[dst,:] += dinv[src]*dinv[dst] * H[src,:]
// One thread = one edge x 4 features (float4 gather, 4 fp32 global atomics).
template <int F, int HID_, int OID>
__global__ void scatter_k(float* __restrict__ Hext,
                          const int* __restrict__ src,
                          const int* __restrict__ dst,
                          float* __restrict__ Oext, int E) {
    const float* H = gbuf<HID_>(Hext);
    float*       O = gbuf<OID>(Oext);
    constexpr int F4 = F / 4;
    long long gid = (long long)blockIdx.x * blockDim.x + threadIdx.x;
    if (gid >= (long long)E * F4) return;
    int e = (int)(gid / F4);
    int f = (int)(gid % F4);
    int s = src[e];
    int d = dst[e];
    float nm = g_dinv[s] * g_dinv[d];
    float4 h = reinterpret_cast<const float4*>(H)[(long long)s * F4 + f];
    float* op = O + (long long)d * F + f * 4;
    atomicAdd(op + 0, h.x * nm);
    atomicAdd(op + 1, h.y * nm);
    atomicAdd(op + 2, h.z * nm);
    atomicAdd(op + 3, h.w * nm);
}

// ---------------------------------------------------------------------------
template <int F, bool RELU, int AID, int OID>
__global__ void bias_k(float* __restrict__ Aext, const float* __restrict__ b,
                       float* __restrict__ Oext, int n) {
    const float* A = gbuf<AID>(Aext);
    float*       O = gbuf<OID>(Oext);
    int gid = blockIdx.x * blockDim.x + threadIdx.x;
    if (gid >= n * F) return;
    float v = A[gid] + b[gid % F];
    O[gid] = RELU ? fmaxf(v, 0.f) : v;
}

// ---------------------------------------------------------------------------
extern "C" void kernel_launch(void* const* d_in, const int* in_sizes, int n_in,
                              void* d_out, int out_size) {
    const float* x   = (const float*)d_in[0];
    const int*   ei  = (const int*)d_in[1];   // int32 [2, E] (JAX x64 disabled)
    const float* W1  = (const float*)d_in[2];
    const float* b1  = (const float*)d_in[3];
    const float* W2  = (const float*)d_in[4];
    const float* b2  = (const float*)d_in[5];
    float*       out = (float*)d_out;

    const int n = in_sizes[0] / FIN;
    const int E = in_sizes[1] / 2;
    const int* src = ei;
    const int* dst = ei + E;

    const int T = 256;
    auto cdiv = [](long long a, long long b) { return (int)((a + b - 1) / b); };

    // degrees + normalization
    deg_init_k <<<cdiv(n, T), T>>>(n);
    deg_count_k<<<cdiv(E, T), T>>>(dst, E);
    dinv_k     <<<cdiv(n, T), T>>>(n);

    // ---- layer 1: FIN=128 -> HID=128, relu ----
    {
        constexpr int RPB = 256 / (HID / 4);
        gemm_k<FIN, HID, 3, 0><<<cdiv(n, RPB), 256>>>(x, nullptr, W1, n);   // X=x ext, O=g_h1
    }
    selfinit_k<HID, 0, 1><<<cdiv((long long)n * (HID/4), T), T>>>(nullptr, nullptr, n);      // g_h1 -> g_agg
    scatter_k <HID, 0, 1><<<cdiv((long long)E * (HID/4), T), T>>>(nullptr, src, dst, nullptr, E);
    bias_k<HID, true, 1, 0><<<cdiv((long long)n * HID, T), T>>>(nullptr, b1, nullptr, n);    // g_h1 = relu(g_agg+b1)

    // ---- layer 2: HID=128 -> FOUT=64, no relu ----
    {
        constexpr int RPB = 256 / (FOUT / 4);
        gemm_k<HID, FOUT, 0, 2><<<cdiv(n, RPB), 256>>>(nullptr, nullptr, W2, n);  // X=g_h1, O=g_h2
    }
    selfinit_k<FOUT, 2, 3><<<cdiv((long long)n * (FOUT/4), T), T>>>(nullptr, out, n);        // g_h2 -> out
    scatter_k <FOUT, 2, 3><<<cdiv((long long)E * (FOUT/4), T), T>>>(nullptr, src, dst, out, E);
    bias_k<FOUT, false, 3, 3><<<cdiv((long long)n * FOUT, T), T>>>(out, b2, out, n);         // out += b2
}

// round 4
// speedup vs baseline: 2.8577x; 2.8577x over previous
#include <cuda_runtime.h>

// ---------------------------------------------------------------------------
// GCNEncoder, CSR-based:
//   dinv[i] = rsqrt(indeg[i] + 1)
//   layer(X,W,b): H = X@W
//     out[i] = dinv[i]^2*H[i] + sum_{e: dst=i} dinv[src]*dinv[i]*H[src] + b
//   out = layer2( relu(layer1(x)) )
// edge_index is int32. Scratch = __device__ globals, no host CUDA API but launches.
// ---------------------------------------------------------------------------

#define MAXN 50048
#define MAXE 800000
#define FIN  128
#define HID  128
#define FOUT 64

__device__ float g_h1 [MAXN * HID];    // GEMM1 out
__device__ float g_agg[MAXN * HID];    // layer1 aggregated+relu
__device__ float g_h2 [MAXN * FOUT];   // GEMM2 out
__device__ float g_dinv[MAXN];
__device__ int   g_deg [MAXN];         // in-degree (no self loop)
__device__ int   g_fill[MAXN];         // bucket fill counters
__device__ int   g_rs  [MAXN + 1];     // CSR row starts (by dst)
__device__ int   g_bsum[256];          // scan partials
__device__ int   g_boff[256];
__device__ int   g_csrc[MAXE];         // CSR src per slot
__device__ float g_cnrm[MAXE];         // CSR edge norm per slot

// ---------------------------------------------------------------------------
__global__ void deg_init_k(int n) {
    int i = blockIdx.x * blockDim.x + threadIdx.x;
    if (i < n) { g_deg[i] = 0; g_fill[i] = 0; }
}

__global__ void deg_count_k(const int* __restrict__ dst, int E) {
    int i = blockIdx.x * blockDim.x + threadIdx.x;
    if (i < E) atomicAdd(&g_deg[dst[i]], 1);
}

__global__ void dinv_k(int n) {
    int i = blockIdx.x * blockDim.x + threadIdx.x;
    if (i < n) g_dinv[i] = rsqrtf((float)(g_deg[i] + 1));
}

// --- 3-kernel exclusive scan of g_deg -> g_rs (256 elems/block) -------------
__global__ void scan1_k(int n) {
    __shared__ int s[256];
    int b = blockIdx.x, t = threadIdx.x;
    int i = b * 256 + t;
    int v = (i < n) ? g_deg[i] : 0;
    s[t] = v;
    __syncthreads();
#pragma unroll
    for (int off = 1; off < 256; off <<= 1) {
        int add = (t >= off) ? s[t - off] : 0;
        __syncthreads();
        s[t] += add;
        __syncthreads();
    }
    if (i <= n) g_rs[i] = s[t] - v;            // exclusive
    if (t == 255) g_bsum[b] = s[255];
}

__global__ void scan2_k(int nb) {
    __shared__ int s[256];
    int t = threadIdx.x;
    int v = (t < nb) ? g_bsum[t] : 0;
    s[t] = v;
    __syncthreads();
#pragma unroll
    for (int off = 1; off < 256; off <<= 1) {
        int add = (t >= off) ? s[t - off] : 0;
        __syncthreads();
        s[t] += add;
        __syncthreads();
    }
    g_boff[t] = s[t] - v;                      // exclusive
}

__global__ void scan3_k(int n, int E) {
    int i = blockIdx.x * blockDim.x + threadIdx.x;
    if (i < n) g_rs[i] += g_boff[i >> 8];
    if (i == 0) g_rs[n] = E;
}

// --- bucket fill: slot = rs[dst] + fill[dst]++ ------------------------------
__global__ void fill_k(const int* __restrict__ src, const int* __restrict__ dst, int E) {
    int e = blockIdx.x * blockDim.x + threadIdx.x;
    if (e >= E) return;
    int d = dst[e], s = src[e];
    int slot = g_rs[d] + atomicAdd(&g_fill[d], 1);
    g_csrc[slot] = s;
    g_cnrm[slot] = g_dinv[s] * g_dinv[d];
}

// ---------------------------------------------------------------------------
// Register-tiled GEMM: O[n,NC] = X[n,K] @ W[K,NC].
// 256 threads; CG = NC/4 col-groups; TG = 256/CG thread-rows; RPT = 64/TG rows
// per thread (stride TG). W float4 loaded once per k-step, reused RPT times.
template <int K, int NC, bool XG, bool OG>
__global__ void __launch_bounds__(256)
gemm_k(const float* __restrict__ Xext, float* __restrict__ Oext,
       const float* __restrict__ W, int n) {
    const float* X = XG ? g_agg : Xext;     // XG: read from g_agg global
    float*       O = OG ? (NC == 128 ? g_h1 : g_h2) : Oext;

    constexpr int CG  = NC / 4;
    constexpr int TG  = 256 / CG;
    constexpr int RPB = 64;
    constexpr int RPT = RPB / TG;
    __shared__ float xs[RPB][K];

    const int row0 = blockIdx.x * RPB;
    // cooperative float4 load of X tile
    {
        const int nf4 = RPB * (K / 4);
        for (int idx = threadIdx.x; idx < nf4; idx += 256) {
            int rr = idx / (K / 4), kk = idx % (K / 4);
            int grow = row0 + rr;
            float4 v = make_float4(0.f, 0.f, 0.f, 0.f);
            if (grow < n) v = reinterpret_cast<const float4*>(X)[(long long)grow * (K / 4) + kk];
            reinterpret_cast<float4*>(&xs[rr][0])[kk] = v;
        }
    }
    __syncthreads();

    const int cg   = threadIdx.x % CG;
    const int trow = threadIdx.x / CG;
    const float4* __restrict__ W4 = reinterpret_cast<const float4*>(W);

    float4 acc[RPT];
#pragma unroll
    for (int r = 0; r < RPT; r++) acc[r] = make_float4(0.f, 0.f, 0.f, 0.f);

#pragma unroll 4
    for (int k4 = 0; k4 < K / 4; k4++) {
        float4 w0 = W4[(k4 * 4 + 0) * CG + cg];
        float4 w1 = W4[(k4 * 4 + 1) * CG + cg];
        float4 w2 = W4[(k4 * 4 + 2) * CG + cg];
        float4 w3 = W4[(k4 * 4 + 3) * CG + cg];
#pragma unroll
        for (int r = 0; r < RPT; r++) {
            float4 xv = reinterpret_cast<const float4*>(&xs[trow + r * TG][0])[k4];
            acc[r].x += xv.x * w0.x + xv.y * w1.x + xv.z * w2.x + xv.w * w3.x;
            acc[r].y += xv.x * w0.y + xv.y * w1.y + xv.z * w2.y + xv.w * w3.y;
            acc[r].z += xv.x * w0.z + xv.y * w1.z + xv.z * w2.z + xv.w * w3.z;
            acc[r].w += xv.x * w0.w + xv.y * w1.w + xv.z * w2.w + xv.w * w3.w;
        }
    }

#pragma unroll
    for (int r = 0; r < RPT; r++) {
        int grow = row0 + trow + r * TG;
        if (grow < n)
            reinterpret_cast<float4*>(O)[(long long)grow * CG + cg] = acc[r];
    }
}

// ---------------------------------------------------------------------------
// CSR aggregation, fused self-loop + bias (+relu):
//   O[i] = dinv[i]^2*H[i] + sum_p cnrm[p]*H[csrc[p]] + b
// GROUP = F/4 lanes per node, float4 per lane.
template <int F, bool RELU, bool HG, bool OG>
__global__ void __launch_bounds__(256)
agg_k(float* __restrict__ Oext, const float* __restrict__ b, int n) {
    const float* H = HG ? g_h1 : g_h2;
    float*       O = OG ? g_agg : Oext;
    constexpr int GROUP = F / 4;              // lanes per node
    int gtid = blockIdx.x * blockDim.x + threadIdx.x;
    int node = gtid / GROUP;
    int lane = gtid % GROUP;
    if (node >= n) return;

    const float4* __restrict__ H4 = reinterpret_cast<const float4*>(H);
    float d = g_dinv[node];
    float s2 = d * d;
    float4 h0 = H4[(long long)node * GROUP + lane];
    float4 acc = make_float4(h0.x * s2, h0.y * s2, h0.z * s2, h0.w * s2);

    int p  = g_rs[node];
    int p1 = g_rs[node + 1];
    for (; p + 1 < p1; p += 2) {
        int   sA = g_csrc[p],     sB = g_csrc[p + 1];
        float nA = g_cnrm[p],     nB = g_cnrm[p + 1];
        float4 hA = H4[(long long)sA * GROUP + lane];
        float4 hB = H4[(long long)sB * GROUP + lane];
        acc.x += nA * hA.x + nB * hB.x;
        acc.y += nA * hA.y + nB * hB.y;
        acc.z += nA * hA.z + nB * hB.z;
        acc.w += nA * hA.w + nB * hB.w;
    }
    if (p < p1) {
        int   s = g_csrc[p];
        float nm = g_cnrm[p];
        float4 h = H4[(long long)s * GROUP + lane];
        acc.x += nm * h.x; acc.y += nm * h.y;
        acc.z += nm * h.z; acc.w += nm * h.w;
    }

    float4 bb = reinterpret_cast<const float4*>(b)[lane];
    acc.x += bb.x; acc.y += bb.y; acc.z += bb.z; acc.w += bb.w;
    if (RELU) {
        acc.x = fmaxf(acc.x, 0.f); acc.y = fmaxf(acc.y, 0.f);
        acc.z = fmaxf(acc.z, 0.f); acc.w = fmaxf(acc.w, 0.f);
    }
    reinterpret_cast<float4*>(O)[(long long)node * GROUP + lane] = acc;
}

// ---------------------------------------------------------------------------
extern "C" void kernel_launch(void* const* d_in, const int* in_sizes, int n_in,
                              void* d_out, int out_size) {
    const float* x   = (const float*)d_in[0];
    const int*   ei  = (const int*)d_in[1];   // int32 [2, E]
    const float* W1  = (const float*)d_in[2];
    const float* b1  = (const float*)d_in[3];
    const float* W2  = (const float*)d_in[4];
    const float* b2  = (const float*)d_in[5];
    float*       out = (float*)d_out;

    const int n = in_sizes[0] / FIN;
    const int E = in_sizes[1] / 2;
    const int* src = ei;
    const int* dst = ei + E;

    const int T = 256;
    auto cdiv = [](long long a, long long b) { return (int)((a + b - 1) / b); };
    const int nb = cdiv(n, 256);

    // CSR build
    deg_init_k <<<cdiv(n, T), T>>>(n);
    deg_count_k<<<cdiv(E, T), T>>>(dst, E);
    dinv_k     <<<cdiv(n, T), T>>>(n);
    scan1_k    <<<nb, 256>>>(n);
    scan2_k    <<<1, 256>>>(nb);
    scan3_k    <<<cdiv(n, T), T>>>(n, E);
    fill_k     <<<cdiv(E, T), T>>>(src, dst, E);

    // layer 1: x @ W1 -> g_h1; aggregate(+b1, relu) -> g_agg
    gemm_k<FIN, HID, false, true><<<cdiv(n, 64), 256>>>(x, nullptr, W1, n);
    agg_k<HID, true, true, true><<<cdiv((long long)n * (HID / 4), T), T>>>(nullptr, b1, n);

    // layer 2: g_agg @ W2 -> g_h2; aggregate(+b2) -> out
    gemm_k<HID, FOUT, true, true><<<cdiv(n, 64), 256>>>(nullptr, nullptr, W2, n);
    agg_k<FOUT, false, false, false><<<cdiv((long long)n * (FOUT / 4), T), T>>>(out, b2, n);
}